// round 16
// baseline (speedup 1.0000x reference)
#include <cuda_runtime.h>
#include <cstdint>

#define B_    32
#define T_    4096
#define D_    256
#define H_    256
#define G4_   1024
#define HOR_  24

typedef unsigned long long ull;

// ---------------- device scratch (static; no runtime allocation) ----------------
__device__ __align__(16) float g_XG[(size_t)B_ * T_ * G4_];   // [m=b*T+t][n] fp32, 512 MB
__device__ __align__(16) float g_h[B_ * H_];                  // final hidden state [b][j]

// ---------------- helpers ----------------
__device__ __forceinline__ ull pack2(float x, float y) {
    ull r;
    asm("mov.b64 %0, {%1, %2};" : "=l"(r) : "f"(x), "f"(y));
    return r;
}
__device__ __forceinline__ void unpack2(ull v, float& x, float& y) {
    asm("mov.b64 {%0, %1}, %2;" : "=f"(x), "=f"(y) : "l"(v));
}
__device__ __forceinline__ ull fma2(ull a, ull w, ull x) {
    asm("fma.rn.f32x2 %0, %1, %2, %0;" : "+l"(a) : "l"(w), "l"(x));
    return a;
}
__device__ __forceinline__ float ex2f(float x) {
    float y; asm("ex2.approx.f32 %0, %1;" : "=f"(y) : "f"(x)); return y;
}
__device__ __forceinline__ float rcpf(float x) {
    float y; asm("rcp.approx.f32 %0, %1;" : "=f"(y) : "f"(x)); return y;
}
__device__ __forceinline__ float sigf(float x) {
    return rcpf(1.f + ex2f(-1.4426950408889634f * x));
}
__device__ __forceinline__ float tanh_f(float x) {
    return fmaf(2.f, rcpf(1.f + ex2f(-2.8853900817779268f * x)), -1.f);
}
__device__ __forceinline__ unsigned smem_u32(const void* p) {
    return (unsigned)__cvta_generic_to_shared(p);
}
__device__ __forceinline__ void mbar_wait_cluster(unsigned mb, unsigned par) {
    asm volatile(
        "{\n\t"
        ".reg .pred P;\n\t"
        "WL_%=:\n\t"
        "mbarrier.try_wait.parity.acquire.cluster.shared::cta.b64 P, [%0], %1, 0x989680;\n\t"
        "@!P bra WL_%=;\n\t"
        "}"
        :: "r"(mb), "r"(par) : "memory");
}

// ---------------- kernel 1: SGEMM  XG[m][n] = A[m][k] @ W[k][n] + bl[n] ----------------
// Tile 128M x 64N, K-tile 16, double-buffered. B staged PRE-DUPLICATED as (b,b) ull
// pairs; inner loop = 4 LDS.128 + 16 FMA2 per k (no packs) -> fma ceiling ~76%.
#define MT 128
#define NT 64
#define KT 16

__global__ void __launch_bounds__(256) k_xgemm(const float* __restrict__ A,
                                               const float* __restrict__ W,
                                               const float* __restrict__ bl) {
    __shared__ __align__(16) float As[2][KT][MT];   // 16 KB
    __shared__ __align__(16) ull   Bs2[2][KT][NT];  // 16 KB, entry n = (b_n, b_n)
    const int tid = threadIdx.x;
    const int m0 = blockIdx.x * MT;
    const int n0 = blockIdx.y * NT;

    const int ar0 = tid >> 2;
    const int akc = (tid & 3) * 4;
    const int bk = tid >> 4;
    const int bn = (tid & 15) * 4;
    const int mt = tid >> 4;
    const int nt = tid & 15;

    const float* Ar0 = A + (size_t)(m0 + ar0) * D_ + akc;
    const float* Ar1 = A + (size_t)(m0 + 64 + ar0) * D_ + akc;
    const float* Wp  = W + (size_t)bk * G4_ + n0 + bn;

    float4 a0 = *(const float4*)(Ar0);
    float4 a1 = *(const float4*)(Ar1);
    float4 b0 = *(const float4*)(Wp);
    #pragma unroll
    for (int i = 0; i < 4; i++) {
        As[0][akc + i][ar0]      = ((const float*)&a0)[i];
        As[0][akc + i][64 + ar0] = ((const float*)&a1)[i];
    }
    {
        ulonglong2 v0, v1;
        v0.x = pack2(b0.x, b0.x); v0.y = pack2(b0.y, b0.y);
        v1.x = pack2(b0.z, b0.z); v1.y = pack2(b0.w, b0.w);
        *(ulonglong2*)&Bs2[0][bk][bn]     = v0;
        *(ulonglong2*)&Bs2[0][bk][bn + 2] = v1;
    }
    __syncthreads();

    ull acc[4][4];
    #pragma unroll
    for (int p = 0; p < 4; p++)
        #pragma unroll
        for (int n = 0; n < 4; n++) acc[p][n] = 0ull;

    #pragma unroll 1
    for (int kt = 0; kt < D_ / KT; kt++) {
        const int cur = kt & 1, nxt = cur ^ 1;
        if (kt + 1 < D_ / KT) {
            a0 = *(const float4*)(Ar0 + (kt + 1) * KT);
            a1 = *(const float4*)(Ar1 + (kt + 1) * KT);
            b0 = *(const float4*)(Wp + (size_t)(kt + 1) * KT * G4_);
        }
        #pragma unroll
        for (int k = 0; k < KT; k++) {
            ulonglong2 a01 = *(const ulonglong2*)&As[cur][k][mt * 8];
            ulonglong2 a23 = *(const ulonglong2*)&As[cur][k][mt * 8 + 4];
            ulonglong2 b01 = *(const ulonglong2*)&Bs2[cur][k][nt * 4];
            ulonglong2 b23 = *(const ulonglong2*)&Bs2[cur][k][nt * 4 + 2];
            acc[0][0] = fma2(acc[0][0], a01.x, b01.x);
            acc[1][0] = fma2(acc[1][0], a01.y, b01.x);
            acc[2][0] = fma2(acc[2][0], a23.x, b01.x);
            acc[3][0] = fma2(acc[3][0], a23.y, b01.x);
            acc[0][1] = fma2(acc[0][1], a01.x, b01.y);
            acc[1][1] = fma2(acc[1][1], a01.y, b01.y);
            acc[2][1] = fma2(acc[2][1], a23.x, b01.y);
            acc[3][1] = fma2(acc[3][1], a23.y, b01.y);
            acc[0][2] = fma2(acc[0][2], a01.x, b23.x);
            acc[1][2] = fma2(acc[1][2], a01.y, b23.x);
            acc[2][2] = fma2(acc[2][2], a23.x, b23.x);
            acc[3][2] = fma2(acc[3][2], a23.y, b23.x);
            acc[0][3] = fma2(acc[0][3], a01.x, b23.y);
            acc[1][3] = fma2(acc[1][3], a01.y, b23.y);
            acc[2][3] = fma2(acc[2][3], a23.x, b23.y);
            acc[3][3] = fma2(acc[3][3], a23.y, b23.y);
        }
        if (kt + 1 < D_ / KT) {
            #pragma unroll
            for (int i = 0; i < 4; i++) {
                As[nxt][akc + i][ar0]      = ((const float*)&a0)[i];
                As[nxt][akc + i][64 + ar0] = ((const float*)&a1)[i];
            }
            ulonglong2 v0, v1;
            v0.x = pack2(b0.x, b0.x); v0.y = pack2(b0.y, b0.y);
            v1.x = pack2(b0.z, b0.z); v1.y = pack2(b0.w, b0.w);
            *(ulonglong2*)&Bs2[nxt][bk][bn]     = v0;
            *(ulonglong2*)&Bs2[nxt][bk][bn + 2] = v1;
            __syncthreads();
        }
    }

    float bias[4];
    #pragma unroll
    for (int n = 0; n < 4; n++) bias[n] = bl[n0 + nt * 4 + n];
    float* Cr = g_XG + (size_t)(m0 + mt * 8) * G4_ + n0 + nt * 4;
    #pragma unroll
    for (int p = 0; p < 4; p++) {
        float e[4], o[4];
        #pragma unroll
        for (int n = 0; n < 4; n++) {
            unpack2(acc[p][n], e[n], o[n]);
            e[n] += bias[n]; o[n] += bias[n];
        }
        *(float4*)(Cr + (size_t)(2 * p) * G4_)     = make_float4(e[0], e[1], e[2], e[3]);
        *(float4*)(Cr + (size_t)(2 * p + 1) * G4_) = make_float4(o[0], o[1], o[2], o[3]);
    }
}

// ---------------- kernel 2: clustered LSTM recurrence (R13 frozen skeleton) ----------------
// 32 clusters x 8 CTAs, occ 2. Cluster g = batch g. CTA rank r owns j in [32r, 32r+32).
// Thread (w = tid>>5, l = tid&31): K-chunk [32w, 32w+32), hidden j = 32r + l, 4 gates.
// Per-source mbars [src][parity]; __syncthreads each step; warp-0 scalar-reduce epilogue.
// h and streamed-weight loads widened to LDS.128.
struct RnnSmem {
    ulonglong2 Wst[8][3][4][32];   // [w][p2][q][l]: .x = pair(20+4p2), .y = pair(22+4p2); 48 KB
    float red[2][8][4][32];        // [par][w][q][l] K-chunk partials, 8 KB
    float hs[2][H_];               // [parity][j] hidden state, 2 KB
    float xg_s[2][4][32];          // [par][q][l] staged XG, 1 KB
    ull   mbar[16];                // [src*2 + parity]
};

__global__ void __launch_bounds__(256, 2) __cluster_dims__(8, 1, 1)
k_rnn(const float* __restrict__ W) {
    extern __shared__ __align__(16) unsigned char smem_raw[];
    RnnSmem* S = (RnnSmem*)smem_raw;

    const int tid = threadIdx.x;
    const int w   = tid >> 5;
    const int l   = tid & 31;
    const int r   = blockIdx.x & 7;
    const int g   = blockIdx.x >> 3;
    const int kbase = w * 32;
    const int j   = r * 32 + l;

    // stationary weights: 40 reg pairs (10 per gate) + 24 streamed pairs (6 per gate, paired)
    ull wreg[40];
    #pragma unroll
    for (int q = 0; q < 4; q++) {
        int n = q * 256 + j;
        #pragma unroll
        for (int p = 0; p < 10; p++) {
            int k = kbase + 2 * p;
            wreg[q * 10 + p] = pack2(W[(size_t)(D_ + k) * G4_ + n],
                                     W[(size_t)(D_ + k + 1) * G4_ + n]);
        }
        #pragma unroll
        for (int p2 = 0; p2 < 3; p2++) {
            int k = kbase + 20 + 4 * p2;
            ulonglong2 v;
            v.x = pack2(W[(size_t)(D_ + k)     * G4_ + n], W[(size_t)(D_ + k + 1) * G4_ + n]);
            v.y = pack2(W[(size_t)(D_ + k + 2) * G4_ + n], W[(size_t)(D_ + k + 3) * G4_ + n]);
            S->Wst[w][p2][q][l] = v;
        }
    }
    for (int i = tid; i < H_; i += 256) S->hs[0][i] = 0.f;
    float c_state = 0.f;   // valid in warp 0

    const unsigned sbase  = smem_u32(S);
    const unsigned hs_off = (unsigned)((char*)&S->hs[0][0] - (char*)S);
    const unsigned mb_off = (unsigned)((char*)&S->mbar[0] - (char*)S);

    if (tid == 0) {
        #pragma unroll
        for (int i = 0; i < 16; i++) {
            asm volatile("mbarrier.init.shared.b64 [%0], 1;"
                         :: "r"(sbase + mb_off + i * 8) : "memory");
        }
        #pragma unroll
        for (int i = 0; i < 16; i++) {
            asm volatile("mbarrier.arrive.expect_tx.shared.b64 _, [%0], 128;"
                         :: "r"(sbase + mb_off + i * 8) : "memory");
        }
    }
    __syncthreads();
    asm volatile("barrier.cluster.arrive.aligned;" ::: "memory");
    asm volatile("barrier.cluster.wait.aligned;"   ::: "memory");

    unsigned rbase[8];
    #pragma unroll
    for (int d = 0; d < 8; d++)
        asm("mapa.shared::cluster.u32 %0, %1, %2;" : "=r"(rbase[d]) : "r"(sbase), "r"(d));

    // XG stream: warp w (w<4) covers gate w: XG[g][t][w*256 + j], one 128B line/warp/step
    const float* xgp = g_XG + ((size_t)g * T_) * G4_ + w * 256 + j;
    float xv = (tid < 128) ? __ldcs(xgp) : 0.f;

    #pragma unroll 1
    for (int t = 0; t < T_; ++t) {
        const int par = t & 1;

        // stage XG + prefetch next (safe before the wait: syncthreads(t+1) provides the lap edge)
        if (tid < 128) {
            S->xg_s[par][w][l] = xv;
            if (t + 1 < T_) xv = __ldcs(xgp + (size_t)(t + 1) * G4_);
        }

        // wait only for the source rank whose h slice this warp consumes
        if (t > 0) {
            const unsigned moff = sbase + mb_off + (unsigned)((w * 2 + ((t - 1) & 1)) * 8);
            mbar_wait_cluster(moff, ((t - 1) >> 1) & 1);
            if (l == 0) {
                asm volatile("mbarrier.arrive.expect_tx.shared.b64 _, [%0], 128;"
                             :: "r"(moff) : "memory");
            }
        }

        const ull* hp = (const ull*)&S->hs[par][kbase];
        ull acc0 = 0, acc1 = 0, acc2 = 0, acc3 = 0;

        // register-weight half: 5 LDS.128 h broadcasts
        #pragma unroll
        for (int p2 = 0; p2 < 5; p2++) {
            ulonglong2 h2 = *(const ulonglong2*)&hp[2 * p2];
            acc0 = fma2(acc0, wreg[2 * p2],      h2.x); acc0 = fma2(acc0, wreg[2 * p2 + 1],      h2.y);
            acc1 = fma2(acc1, wreg[10 + 2 * p2], h2.x); acc1 = fma2(acc1, wreg[10 + 2 * p2 + 1], h2.y);
            acc2 = fma2(acc2, wreg[20 + 2 * p2], h2.x); acc2 = fma2(acc2, wreg[20 + 2 * p2 + 1], h2.y);
            acc3 = fma2(acc3, wreg[30 + 2 * p2], h2.x); acc3 = fma2(acc3, wreg[30 + 2 * p2 + 1], h2.y);
        }
        // streamed-weight half: 3 LDS.128 h broadcasts + 12 LDS.128 weights
        const ulonglong2* wst = &S->Wst[w][0][0][l];
        #pragma unroll
        for (int p2 = 0; p2 < 3; p2++) {
            ulonglong2 h2 = *(const ulonglong2*)&hp[10 + 2 * p2];
            ulonglong2 w0 = wst[p2 * 128 + 0];
            ulonglong2 w1 = wst[p2 * 128 + 32];
            ulonglong2 w2 = wst[p2 * 128 + 64];
            ulonglong2 w3 = wst[p2 * 128 + 96];
            acc0 = fma2(acc0, w0.x, h2.x); acc0 = fma2(acc0, w0.y, h2.y);
            acc1 = fma2(acc1, w1.x, h2.x); acc1 = fma2(acc1, w1.y, h2.y);
            acc2 = fma2(acc2, w2.x, h2.x); acc2 = fma2(acc2, w2.y, h2.y);
            acc3 = fma2(acc3, w3.x, h2.x); acc3 = fma2(acc3, w3.y, h2.y);
        }

        {
            float ax, ay;
            unpack2(acc0, ax, ay); S->red[par][w][0][l] = ax + ay;
            unpack2(acc1, ax, ay); S->red[par][w][1][l] = ax + ay;
            unpack2(acc2, ax, ay); S->red[par][w][2][l] = ax + ay;
            unpack2(acc3, ax, ay); S->red[par][w][3][l] = ax + ay;
        }
        __syncthreads();

        // warp 0: reduce over 8 K-chunks, activations, per-source DSMEM broadcast
        if (w == 0) {
            float gsum[4];
            #pragma unroll
            for (int q = 0; q < 4; q++) {
                float s = S->xg_s[par][q][l];
                #pragma unroll
                for (int kh2 = 0; kh2 < 8; kh2++) s += S->red[par][kh2][q][l];
                gsum[q] = s;
            }
            c_state = sigf(gsum[2] + 1.f) * c_state + sigf(gsum[0]) * tanh_f(gsum[1]);
            float h = sigf(gsum[3]) * tanh_f(c_state);
            unsigned hbits = __float_as_uint(h);

            if (t + 1 < T_) {
                const unsigned dst_off = hs_off + (unsigned)((((t + 1) & 1) * H_ + j) * 4);
                const unsigned mbr_off = mb_off + (unsigned)((r * 2 + par) * 8);
                #pragma unroll
                for (int d = 0; d < 8; d++) {
                    asm volatile(
                        "st.async.weak.shared::cluster.mbarrier::complete_tx::bytes.u32 [%0], %1, [%2];"
                        :: "r"(rbase[d] + dst_off), "r"(hbits), "r"(rbase[d] + mbr_off)
                        : "memory");
                }
            } else {
                g_h[g * H_ + j] = h;
            }
        }
    }
    // no drain needed: every issued store is consumed by a receiver wait before exit
}

// ---------------- kernel 3: out = (h @ Wfc + bfc) @ Wout + bout ----------------
__global__ void __launch_bounds__(256) k_fc(const float* __restrict__ Wfc,
                                            const float* __restrict__ bfc,
                                            const float* __restrict__ Wout,
                                            const float* __restrict__ bout,
                                            float* __restrict__ out) {
    __shared__ float tmp[H_];
    int b = blockIdx.x;
    int jj = threadIdx.x;
    const float* h = &g_h[b * H_];
    float s = bfc[jj];
    #pragma unroll 8
    for (int k = 0; k < H_; k++) s += h[k] * Wfc[(size_t)k * H_ + jj];
    tmp[jj] = s;
    __syncthreads();
    if (jj < HOR_) {
        float o = bout[jj];
        #pragma unroll 8
        for (int k = 0; k < H_; k++) o += tmp[k] * Wout[(size_t)k * HOR_ + jj];
        out[b * HOR_ + jj] = o;
    }
}

// ---------------- launch ----------------
extern "C" void kernel_launch(void* const* d_in, const int* in_sizes, int n_in,
                              void* d_out, int out_size) {
    const float* x      = (const float*)d_in[0];
    const float* W_lstm = (const float*)d_in[1];
    const float* b_lstm = (const float*)d_in[2];
    const float* W_fc   = (const float*)d_in[3];
    const float* b_fc   = (const float*)d_in[4];
    const float* W_out  = (const float*)d_in[5];
    const float* b_out  = (const float*)d_in[6];
    float* out = (float*)d_out;

    cudaFuncSetAttribute(k_rnn, cudaFuncAttributeMaxDynamicSharedMemorySize,
                         (int)sizeof(RnnSmem));

    k_xgemm<<<dim3((B_ * T_) / MT, G4_ / NT), 256>>>(x, W_lstm, b_lstm);
    k_rnn<<<256, 256, sizeof(RnnSmem)>>>(W_lstm);
    k_fc<<<B_, 256>>>(W_fc, b_fc, W_out, b_out, out);
}

// round 17
// speedup vs baseline: 1.1453x; 1.1453x over previous
#include <cuda_runtime.h>
#include <cstdint>

#define B_    32
#define T_    4096
#define D_    256
#define H_    256
#define G4_   1024
#define HOR_  24

typedef unsigned long long ull;

// ---------------- device scratch (static; no runtime allocation) ----------------
__device__ __align__(16) float g_XG[(size_t)B_ * T_ * G4_];   // [m=b*T+t][n] fp32, 512 MB
__device__ __align__(16) float g_h[B_ * H_];                  // final hidden state [b][j]

// ---------------- helpers ----------------
__device__ __forceinline__ ull pack2(float x, float y) {
    ull r;
    asm("mov.b64 %0, {%1, %2};" : "=l"(r) : "f"(x), "f"(y));
    return r;
}
__device__ __forceinline__ void unpack2(ull v, float& x, float& y) {
    asm("mov.b64 {%0, %1}, %2;" : "=f"(x), "=f"(y) : "l"(v));
}
__device__ __forceinline__ ull fma2(ull a, ull w, ull x) {
    asm("fma.rn.f32x2 %0, %1, %2, %0;" : "+l"(a) : "l"(w), "l"(x));
    return a;
}
__device__ __forceinline__ float ex2f(float x) {
    float y; asm("ex2.approx.f32 %0, %1;" : "=f"(y) : "f"(x)); return y;
}
__device__ __forceinline__ float rcpf(float x) {
    float y; asm("rcp.approx.f32 %0, %1;" : "=f"(y) : "f"(x)); return y;
}
__device__ __forceinline__ float sigf(float x) {
    return rcpf(1.f + ex2f(-1.4426950408889634f * x));
}
__device__ __forceinline__ float tanh_f(float x) {
    return fmaf(2.f, rcpf(1.f + ex2f(-2.8853900817779268f * x)), -1.f);
}
__device__ __forceinline__ unsigned smem_u32(const void* p) {
    return (unsigned)__cvta_generic_to_shared(p);
}
__device__ __forceinline__ void mbar_wait_cluster(unsigned mb, unsigned par) {
    asm volatile(
        "{\n\t"
        ".reg .pred P;\n\t"
        "WL_%=:\n\t"
        "mbarrier.try_wait.parity.acquire.cluster.shared::cta.b64 P, [%0], %1, 0x989680;\n\t"
        "@!P bra WL_%=;\n\t"
        "}"
        :: "r"(mb), "r"(par) : "memory");
}

// ---------------- kernel 1: SGEMM  XG[m][n] = A[m][k] @ W[k][n] + bl[n] ----------------
// Tile 128M x 64N, K-tile 16, double-buffered. B pre-duplicated as (b,b) ull.
// Thread nt's n-columns SPLIT: {2nt, 2nt+1} and {32+2nt, 33+2nt} -> B reads are
// ulonglong2 at byte 16*nt (+256): 2-wavefront floor, ZERO bank-conflict penalty.
// Inner loop per k: 2 A-LDS.128 + 2 B-LDS.128 + 16 FMA2, no packs (80% fma ceiling).
#define MT 128
#define NT 64
#define KT 16

__global__ void __launch_bounds__(256) k_xgemm(const float* __restrict__ A,
                                               const float* __restrict__ W,
                                               const float* __restrict__ bl) {
    __shared__ __align__(16) float As[2][KT][MT];   // 16 KB
    __shared__ __align__(16) ull   Bs2[2][KT][NT];  // 16 KB, entry n = (b_n, b_n)
    const int tid = threadIdx.x;
    const int m0 = blockIdx.x * MT;
    const int n0 = blockIdx.y * NT;

    const int ar0 = tid >> 2;
    const int akc = (tid & 3) * 4;
    const int bk = tid >> 4;
    const int bn = (tid & 15) * 4;
    const int mt = tid >> 4;
    const int nt = tid & 15;

    const float* Ar0 = A + (size_t)(m0 + ar0) * D_ + akc;
    const float* Ar1 = A + (size_t)(m0 + 64 + ar0) * D_ + akc;
    const float* Wp  = W + (size_t)bk * G4_ + n0 + bn;

    float4 a0 = *(const float4*)(Ar0);
    float4 a1 = *(const float4*)(Ar1);
    float4 b0 = *(const float4*)(Wp);
    #pragma unroll
    for (int i = 0; i < 4; i++) {
        As[0][akc + i][ar0]      = ((const float*)&a0)[i];
        As[0][akc + i][64 + ar0] = ((const float*)&a1)[i];
    }
    {
        ulonglong2 v0, v1;
        v0.x = pack2(b0.x, b0.x); v0.y = pack2(b0.y, b0.y);
        v1.x = pack2(b0.z, b0.z); v1.y = pack2(b0.w, b0.w);
        *(ulonglong2*)&Bs2[0][bk][bn]     = v0;
        *(ulonglong2*)&Bs2[0][bk][bn + 2] = v1;
    }
    __syncthreads();

    // acc[p][ni]: ni 0,1 -> n = 2nt+ni ; ni 2,3 -> n = 32+2nt+(ni-2). p = M pair row.
    ull acc[4][4];
    #pragma unroll
    for (int p = 0; p < 4; p++)
        #pragma unroll
        for (int n = 0; n < 4; n++) acc[p][n] = 0ull;

    #pragma unroll 1
    for (int kt = 0; kt < D_ / KT; kt++) {
        const int cur = kt & 1, nxt = cur ^ 1;
        if (kt + 1 < D_ / KT) {
            a0 = *(const float4*)(Ar0 + (kt + 1) * KT);
            a1 = *(const float4*)(Ar1 + (kt + 1) * KT);
            b0 = *(const float4*)(Wp + (size_t)(kt + 1) * KT * G4_);
        }
        #pragma unroll
        for (int k = 0; k < KT; k++) {
            ulonglong2 a01 = *(const ulonglong2*)&As[cur][k][mt * 8];
            ulonglong2 a23 = *(const ulonglong2*)&As[cur][k][mt * 8 + 4];
            ulonglong2 bA  = *(const ulonglong2*)&Bs2[cur][k][nt * 2];        // n = 2nt, 2nt+1
            ulonglong2 bB  = *(const ulonglong2*)&Bs2[cur][k][32 + nt * 2];   // n = 32+2nt, 33+2nt
            acc[0][0] = fma2(acc[0][0], a01.x, bA.x);
            acc[1][0] = fma2(acc[1][0], a01.y, bA.x);
            acc[2][0] = fma2(acc[2][0], a23.x, bA.x);
            acc[3][0] = fma2(acc[3][0], a23.y, bA.x);
            acc[0][1] = fma2(acc[0][1], a01.x, bA.y);
            acc[1][1] = fma2(acc[1][1], a01.y, bA.y);
            acc[2][1] = fma2(acc[2][1], a23.x, bA.y);
            acc[3][1] = fma2(acc[3][1], a23.y, bA.y);
            acc[0][2] = fma2(acc[0][2], a01.x, bB.x);
            acc[1][2] = fma2(acc[1][2], a01.y, bB.x);
            acc[2][2] = fma2(acc[2][2], a23.x, bB.x);
            acc[3][2] = fma2(acc[3][2], a23.y, bB.x);
            acc[0][3] = fma2(acc[0][3], a01.x, bB.y);
            acc[1][3] = fma2(acc[1][3], a01.y, bB.y);
            acc[2][3] = fma2(acc[2][3], a23.x, bB.y);
            acc[3][3] = fma2(acc[3][3], a23.y, bB.y);
        }
        if (kt + 1 < D_ / KT) {
            #pragma unroll
            for (int i = 0; i < 4; i++) {
                As[nxt][akc + i][ar0]      = ((const float*)&a0)[i];
                As[nxt][akc + i][64 + ar0] = ((const float*)&a1)[i];
            }
            ulonglong2 v0, v1;
            v0.x = pack2(b0.x, b0.x); v0.y = pack2(b0.y, b0.y);
            v1.x = pack2(b0.z, b0.z); v1.y = pack2(b0.w, b0.w);
            *(ulonglong2*)&Bs2[nxt][bk][bn]     = v0;
            *(ulonglong2*)&Bs2[nxt][bk][bn + 2] = v1;
            __syncthreads();
        }
    }

    // epilogue: two float2 segments per row (n = 2nt and n = 32+2nt)
    float biasA0 = bl[n0 + 2 * nt],      biasA1 = bl[n0 + 2 * nt + 1];
    float biasB0 = bl[n0 + 32 + 2 * nt], biasB1 = bl[n0 + 32 + 2 * nt + 1];
    float* Cr = g_XG + (size_t)(m0 + mt * 8) * G4_ + n0;
    #pragma unroll
    for (int p = 0; p < 4; p++) {
        float eA0, oA0, eA1, oA1, eB0, oB0, eB1, oB1;
        unpack2(acc[p][0], eA0, oA0);
        unpack2(acc[p][1], eA1, oA1);
        unpack2(acc[p][2], eB0, oB0);
        unpack2(acc[p][3], eB1, oB1);
        float* r0 = Cr + (size_t)(2 * p) * G4_;
        float* r1 = Cr + (size_t)(2 * p + 1) * G4_;
        *(float2*)(r0 + 2 * nt)      = make_float2(eA0 + biasA0, eA1 + biasA1);
        *(float2*)(r0 + 32 + 2 * nt) = make_float2(eB0 + biasB0, eB1 + biasB1);
        *(float2*)(r1 + 2 * nt)      = make_float2(oA0 + biasA0, oA1 + biasA1);
        *(float2*)(r1 + 32 + 2 * nt) = make_float2(oB0 + biasB0, oB1 + biasB1);
    }
}

// ---------------- kernel 2: clustered LSTM recurrence (R13 frozen skeleton) ----------------
// 32 clusters x 8 CTAs, occ 2. Cluster g = batch g. CTA rank r owns j in [32r, 32r+32).
// Thread (w = tid>>5, l = tid&31): K-chunk [32w, 32w+32), hidden j = 32r + l, 4 gates.
// Per-source mbars [src][parity]; __syncthreads each step; warp-0 scalar-reduce epilogue.
// h and streamed-weight loads widened to LDS.128.
struct RnnSmem {
    ulonglong2 Wst[8][3][4][32];   // [w][p2][q][l]: .x = pair(20+4p2), .y = pair(22+4p2); 48 KB
    float red[2][8][4][32];        // [par][w][q][l] K-chunk partials, 8 KB
    float hs[2][H_];               // [parity][j] hidden state, 2 KB
    float xg_s[2][4][32];          // [par][q][l] staged XG, 1 KB
    ull   mbar[16];                // [src*2 + parity]
};

__global__ void __launch_bounds__(256, 2) __cluster_dims__(8, 1, 1)
k_rnn(const float* __restrict__ W) {
    extern __shared__ __align__(16) unsigned char smem_raw[];
    RnnSmem* S = (RnnSmem*)smem_raw;

    const int tid = threadIdx.x;
    const int w   = tid >> 5;
    const int l   = tid & 31;
    const int r   = blockIdx.x & 7;
    const int g   = blockIdx.x >> 3;
    const int kbase = w * 32;
    const int j   = r * 32 + l;

    // stationary weights: 40 reg pairs (10 per gate) + 24 streamed pairs (6 per gate, paired)
    ull wreg[40];
    #pragma unroll
    for (int q = 0; q < 4; q++) {
        int n = q * 256 + j;
        #pragma unroll
        for (int p = 0; p < 10; p++) {
            int k = kbase + 2 * p;
            wreg[q * 10 + p] = pack2(W[(size_t)(D_ + k) * G4_ + n],
                                     W[(size_t)(D_ + k + 1) * G4_ + n]);
        }
        #pragma unroll
        for (int p2 = 0; p2 < 3; p2++) {
            int k = kbase + 20 + 4 * p2;
            ulonglong2 v;
            v.x = pack2(W[(size_t)(D_ + k)     * G4_ + n], W[(size_t)(D_ + k + 1) * G4_ + n]);
            v.y = pack2(W[(size_t)(D_ + k + 2) * G4_ + n], W[(size_t)(D_ + k + 3) * G4_ + n]);
            S->Wst[w][p2][q][l] = v;
        }
    }
    for (int i = tid; i < H_; i += 256) S->hs[0][i] = 0.f;
    float c_state = 0.f;   // valid in warp 0

    const unsigned sbase  = smem_u32(S);
    const unsigned hs_off = (unsigned)((char*)&S->hs[0][0] - (char*)S);
    const unsigned mb_off = (unsigned)((char*)&S->mbar[0] - (char*)S);

    if (tid == 0) {
        #pragma unroll
        for (int i = 0; i < 16; i++) {
            asm volatile("mbarrier.init.shared.b64 [%0], 1;"
                         :: "r"(sbase + mb_off + i * 8) : "memory");
        }
        #pragma unroll
        for (int i = 0; i < 16; i++) {
            asm volatile("mbarrier.arrive.expect_tx.shared.b64 _, [%0], 128;"
                         :: "r"(sbase + mb_off + i * 8) : "memory");
        }
    }
    __syncthreads();
    asm volatile("barrier.cluster.arrive.aligned;" ::: "memory");
    asm volatile("barrier.cluster.wait.aligned;"   ::: "memory");

    unsigned rbase[8];
    #pragma unroll
    for (int d = 0; d < 8; d++)
        asm("mapa.shared::cluster.u32 %0, %1, %2;" : "=r"(rbase[d]) : "r"(sbase), "r"(d));

    // XG stream: warp w (w<4) covers gate w: XG[g][t][w*256 + j], one 128B line/warp/step
    const float* xgp = g_XG + ((size_t)g * T_) * G4_ + w * 256 + j;
    float xv = (tid < 128) ? __ldcs(xgp) : 0.f;

    #pragma unroll 1
    for (int t = 0; t < T_; ++t) {
        const int par = t & 1;

        // stage XG + prefetch next (safe before the wait: syncthreads(t+1) provides the lap edge)
        if (tid < 128) {
            S->xg_s[par][w][l] = xv;
            if (t + 1 < T_) xv = __ldcs(xgp + (size_t)(t + 1) * G4_);
        }

        // wait only for the source rank whose h slice this warp consumes
        if (t > 0) {
            const unsigned moff = sbase + mb_off + (unsigned)((w * 2 + ((t - 1) & 1)) * 8);
            mbar_wait_cluster(moff, ((t - 1) >> 1) & 1);
            if (l == 0) {
                asm volatile("mbarrier.arrive.expect_tx.shared.b64 _, [%0], 128;"
                             :: "r"(moff) : "memory");
            }
        }

        const ull* hp = (const ull*)&S->hs[par][kbase];
        ull acc0 = 0, acc1 = 0, acc2 = 0, acc3 = 0;

        // register-weight half: 5 LDS.128 h broadcasts
        #pragma unroll
        for (int p2 = 0; p2 < 5; p2++) {
            ulonglong2 h2 = *(const ulonglong2*)&hp[2 * p2];
            acc0 = fma2(acc0, wreg[2 * p2],      h2.x); acc0 = fma2(acc0, wreg[2 * p2 + 1],      h2.y);
            acc1 = fma2(acc1, wreg[10 + 2 * p2], h2.x); acc1 = fma2(acc1, wreg[10 + 2 * p2 + 1], h2.y);
            acc2 = fma2(acc2, wreg[20 + 2 * p2], h2.x); acc2 = fma2(acc2, wreg[20 + 2 * p2 + 1], h2.y);
            acc3 = fma2(acc3, wreg[30 + 2 * p2], h2.x); acc3 = fma2(acc3, wreg[30 + 2 * p2 + 1], h2.y);
        }
        // streamed-weight half: 3 LDS.128 h broadcasts + 12 LDS.128 weights
        const ulonglong2* wst = &S->Wst[w][0][0][l];
        #pragma unroll
        for (int p2 = 0; p2 < 3; p2++) {
            ulonglong2 h2 = *(const ulonglong2*)&hp[10 + 2 * p2];
            ulonglong2 w0 = wst[p2 * 128 + 0];
            ulonglong2 w1 = wst[p2 * 128 + 32];
            ulonglong2 w2 = wst[p2 * 128 + 64];
            ulonglong2 w3 = wst[p2 * 128 + 96];
            acc0 = fma2(acc0, w0.x, h2.x); acc0 = fma2(acc0, w0.y, h2.y);
            acc1 = fma2(acc1, w1.x, h2.x); acc1 = fma2(acc1, w1.y, h2.y);
            acc2 = fma2(acc2, w2.x, h2.x); acc2 = fma2(acc2, w2.y, h2.y);
            acc3 = fma2(acc3, w3.x, h2.x); acc3 = fma2(acc3, w3.y, h2.y);
        }

        {
            float ax, ay;
            unpack2(acc0, ax, ay); S->red[par][w][0][l] = ax + ay;
            unpack2(acc1, ax, ay); S->red[par][w][1][l] = ax + ay;
            unpack2(acc2, ax, ay); S->red[par][w][2][l] = ax + ay;
            unpack2(acc3, ax, ay); S->red[par][w][3][l] = ax + ay;
        }
        __syncthreads();

        // warp 0: reduce over 8 K-chunks, activations, per-source DSMEM broadcast
        if (w == 0) {
            float gsum[4];
            #pragma unroll
            for (int q = 0; q < 4; q++) {
                float s = S->xg_s[par][q][l];
                #pragma unroll
                for (int kh2 = 0; kh2 < 8; kh2++) s += S->red[par][kh2][q][l];
                gsum[q] = s;
            }
            c_state = sigf(gsum[2] + 1.f) * c_state + sigf(gsum[0]) * tanh_f(gsum[1]);
            float h = sigf(gsum[3]) * tanh_f(c_state);
            unsigned hbits = __float_as_uint(h);

            if (t + 1 < T_) {
                const unsigned dst_off = hs_off + (unsigned)((((t + 1) & 1) * H_ + j) * 4);
                const unsigned mbr_off = mb_off + (unsigned)((r * 2 + par) * 8);
                #pragma unroll
                for (int d = 0; d < 8; d++) {
                    asm volatile(
                        "st.async.weak.shared::cluster.mbarrier::complete_tx::bytes.u32 [%0], %1, [%2];"
                        :: "r"(rbase[d] + dst_off), "r"(hbits), "r"(rbase[d] + mbr_off)
                        : "memory");
                }
            } else {
                g_h[g * H_ + j] = h;
            }
        }
    }
    // no drain needed: every issued store is consumed by a receiver wait before exit
}

// ---------------- kernel 3: out = (h @ Wfc + bfc) @ Wout + bout ----------------
__global__ void __launch_bounds__(256) k_fc(const float* __restrict__ Wfc,
                                            const float* __restrict__ bfc,
                                            const float* __restrict__ Wout,
                                            const float* __restrict__ bout,
                                            float* __restrict__ out) {
    __shared__ float tmp[H_];
    int b = blockIdx.x;
    int jj = threadIdx.x;
    const float* h = &g_h[b * H_];
    float s = bfc[jj];
    #pragma unroll 8
    for (int k = 0; k < H_; k++) s += h[k] * Wfc[(size_t)k * H_ + jj];
    tmp[jj] = s;
    __syncthreads();
    if (jj < HOR_) {
        float o = bout[jj];
        #pragma unroll 8
        for (int k = 0; k < H_; k++) o += tmp[k] * Wout[(size_t)k * HOR_ + jj];
        out[b * HOR_ + jj] = o;
    }
}

// ---------------- launch ----------------
extern "C" void kernel_launch(void* const* d_in, const int* in_sizes, int n_in,
                              void* d_out, int out_size) {
    const float* x      = (const float*)d_in[0];
    const float* W_lstm = (const float*)d_in[1];
    const float* b_lstm = (const float*)d_in[2];
    const float* W_fc   = (const float*)d_in[3];
    const float* b_fc   = (const float*)d_in[4];
    const float* W_out  = (const float*)d_in[5];
    const float* b_out  = (const float*)d_in[6];
    float* out = (float*)d_out;

    cudaFuncSetAttribute(k_rnn, cudaFuncAttributeMaxDynamicSharedMemorySize,
                         (int)sizeof(RnnSmem));

    k_xgemm<<<dim3((B_ * T_) / MT, G4_ / NT), 256>>>(x, W_lstm, b_lstm);
    k_rnn<<<256, 256, sizeof(RnnSmem)>>>(W_lstm);
    k_fc<<<B_, 256>>>(W_fc, b_fc, W_out, b_out, out);
}